// round 14
// baseline (speedup 1.0000x reference)
#include <cuda_runtime.h>
#include <math.h>

// Fixed problem shapes (from setup_inputs)
#define BB   8
#define TT   64
#define RR   100
#define TH   768
#define IH   1024
#define PP   512

// Final activations
__device__ float g_q[BB * TT * PP];          // [512][512]
__device__ float g_k[BB * RR * PP];          // [800][512]
// Split-K partials: uniform 128-wide K-chunks (q: 6 chunks, k: 8 chunks)
#define QSPLIT 6
#define KSPLIT 8
__device__ float g_pq[QSPLIT * BB * TT * PP];
__device__ float g_pk[KSPLIT * BB * RR * PP];

typedef unsigned long long ull;

// ---------------- f32x2 helpers (Blackwell packed fp32) -----------------------
__device__ __forceinline__ ull ffma2(ull a, ull b, ull c) {
    ull d;
    asm("fma.rn.f32x2 %0, %1, %2, %3;" : "=l"(d) : "l"(a), "l"(b), "l"(c));
    return d;
}
__device__ __forceinline__ float2 unpack2(ull v) {
    float2 f;
    asm("mov.b64 {%0, %1}, %2;" : "=f"(f.x), "=f"(f.y) : "l"(v));
    return f;
}
__device__ __forceinline__ ull dup2(float x) {
    ull r;
    asm("mov.b64 %0, {%1, %1};" : "=l"(r) : "f"(x));
    return r;
}

__device__ __forceinline__ float gelu_exact(float x) {
    return 0.5f * x * (1.0f + erff(x * 0.70710678118654752440f));
}

__device__ __forceinline__ float tanh_approx(float x) {
    float y;
    asm("tanh.approx.f32 %0, %1;" : "=f"(y) : "f"(x));
    return y;
}

// ---------------- Kernel 1: split-K GEMM, 16x4 M-heavy microtile --------------
// Block tile 128(M) x 64(N) x 16(K), 128 threads, thread = 16 rows x 4 cols.
// L1-wavefront diet: per warp-kk  A = 4 broadcast LDS.128 (128 B unique),
// B = 1 contiguous LDS.128 (256 B unique) + 4 dup2 splats, 32 FFMA2.
// ~6 wavefronts per 64 FMA-cyc (was 10) -> FMA pipe becomes the binder.
//   blocks [0,448)   : k-GEMM encI[800,1024] @ Wk  (7x8 tiles x 8 chunks)
//   blocks [448,640) : q-GEMM encT[512,768]  @ Wq  (4x8 tiles x 6 chunks)
#define GBM 128
#define GBN 64
#define GBK 16
#define KCHUNK 128

__global__ __launch_bounds__(128, 4) void gemm_part_kernel(
    const float* __restrict__ encT, const float* __restrict__ Wq,
    const float* __restrict__ encI, const float* __restrict__ Wk)
{
    __shared__ __align__(16) float Ast[2][GBK][GBM + 4];   // transposed A, stride 132
    __shared__ __align__(16) float Ws[2][GBK][GBN];

    int bid = blockIdx.x;
    const float* A; const float* W; float* Cp;
    int K, Mrows, tile, half;
    if (bid < 448) {
        tile = bid >> 3; half = bid & 7;
        A = encI; W = Wk; K = IH; Mrows = BB * RR;           // 800
        Cp = g_pk + half * (BB * RR * PP);
    } else {
        bid -= 448;
        tile = bid / QSPLIT; half = bid - tile * QSPLIT;
        A = encT; W = Wq; K = TH; Mrows = BB * TT;           // 512
        Cp = g_pq + half * (BB * TT * PP);
    }
    const int mt = tile >> 3, nt = tile & 7;
    const int m0 = mt * GBM;
    const int n0 = nt * GBN;
    const int kstart = half * KCHUNK;
    const int niter = KCHUNK / GBK;      // 8, uniform

    const int tid = threadIdx.x;
    const int tx = tid & 15;     // cols tx*4 .. +3
    const int ty = tid >> 4;     // rows ty*16 .. +15 (8 row-pairs)

    // A loader: 4 phases of 512 floats over [128 rows][16 k]
    //   flat = ph*512 + tid*4 -> r = flat>>4, c = flat&15
    const int ar = tid >> 2;                 // + ph*32
    const int ac = (tid & 3) * 4;
    int arow[4];
    #pragma unroll
    for (int p = 0; p < 4; p++) arow[p] = min(m0 + ar + p * 32, Mrows - 1);
    // W loader: 2 phases of 512 floats over [16 k][64 n]
    //   kk = tid>>4 (+ph*8), n = (tid*4)&63
    const int wk = tid >> 4;
    const int wn = (tid * 4) & 63;

    ull acc[8][4];               // [rowpair][col]
    #pragma unroll
    for (int i = 0; i < 8; i++)
        #pragma unroll
        for (int j = 0; j < 4; j++) acc[i][j] = 0ull;

    float4 pa[4], pw0, pw1;

    #define LOAD_TILE(k0)                                            \
    {   pa[0] = *(const float4*)&A[arow[0] * K + (k0) + ac];         \
        pa[1] = *(const float4*)&A[arow[1] * K + (k0) + ac];         \
        pa[2] = *(const float4*)&A[arow[2] * K + (k0) + ac];         \
        pa[3] = *(const float4*)&A[arow[3] * K + (k0) + ac];         \
        pw0 = *(const float4*)&W[((k0) + wk + 0) * PP + n0 + wn];    \
        pw1 = *(const float4*)&W[((k0) + wk + 8) * PP + n0 + wn]; }

    #define STORE_TILE(buf)                                          \
    {   _Pragma("unroll")                                            \
        for (int p = 0; p < 4; p++) {                                \
            Ast[buf][ac + 0][ar + p * 32] = pa[p].x;                 \
            Ast[buf][ac + 1][ar + p * 32] = pa[p].y;                 \
            Ast[buf][ac + 2][ar + p * 32] = pa[p].z;                 \
            Ast[buf][ac + 3][ar + p * 32] = pa[p].w;                 \
        }                                                            \
        *(float4*)&Ws[buf][wk + 0][wn] = pw0;                        \
        *(float4*)&Ws[buf][wk + 8][wn] = pw1; }

    LOAD_TILE(kstart)
    STORE_TILE(0)

    for (int it = 0; it < niter; it++) {
        __syncthreads();
        const int cur = it & 1;

        const bool more = (it + 1) < niter;
        if (more) LOAD_TILE(kstart + (it + 1) * GBK)

        #pragma unroll
        for (int kk = 0; kk < GBK; kk++) {
            // 8 row-pairs, pre-packed: 4 broadcast LDS.128
            ulonglong2 a01 = *(const ulonglong2*)&Ast[cur][kk][ty * 16];
            ulonglong2 a23 = *(const ulonglong2*)&Ast[cur][kk][ty * 16 + 4];
            ulonglong2 a45 = *(const ulonglong2*)&Ast[cur][kk][ty * 16 + 8];
            ulonglong2 a67 = *(const ulonglong2*)&Ast[cur][kk][ty * 16 + 12];
            // 4 cols: 1 contiguous LDS.128 + 4 splats
            float4 bv = *(const float4*)&Ws[cur][kk][tx * 4];
            ull s0 = dup2(bv.x), s1 = dup2(bv.y), s2 = dup2(bv.z), s3 = dup2(bv.w);

            acc[0][0] = ffma2(a01.x, s0, acc[0][0]);
            acc[0][1] = ffma2(a01.x, s1, acc[0][1]);
            acc[0][2] = ffma2(a01.x, s2, acc[0][2]);
            acc[0][3] = ffma2(a01.x, s3, acc[0][3]);
            acc[1][0] = ffma2(a01.y, s0, acc[1][0]);
            acc[1][1] = ffma2(a01.y, s1, acc[1][1]);
            acc[1][2] = ffma2(a01.y, s2, acc[1][2]);
            acc[1][3] = ffma2(a01.y, s3, acc[1][3]);
            acc[2][0] = ffma2(a23.x, s0, acc[2][0]);
            acc[2][1] = ffma2(a23.x, s1, acc[2][1]);
            acc[2][2] = ffma2(a23.x, s2, acc[2][2]);
            acc[2][3] = ffma2(a23.x, s3, acc[2][3]);
            acc[3][0] = ffma2(a23.y, s0, acc[3][0]);
            acc[3][1] = ffma2(a23.y, s1, acc[3][1]);
            acc[3][2] = ffma2(a23.y, s2, acc[3][2]);
            acc[3][3] = ffma2(a23.y, s3, acc[3][3]);
            acc[4][0] = ffma2(a45.x, s0, acc[4][0]);
            acc[4][1] = ffma2(a45.x, s1, acc[4][1]);
            acc[4][2] = ffma2(a45.x, s2, acc[4][2]);
            acc[4][3] = ffma2(a45.x, s3, acc[4][3]);
            acc[5][0] = ffma2(a45.y, s0, acc[5][0]);
            acc[5][1] = ffma2(a45.y, s1, acc[5][1]);
            acc[5][2] = ffma2(a45.y, s2, acc[5][2]);
            acc[5][3] = ffma2(a45.y, s3, acc[5][3]);
            acc[6][0] = ffma2(a67.x, s0, acc[6][0]);
            acc[6][1] = ffma2(a67.x, s1, acc[6][1]);
            acc[6][2] = ffma2(a67.x, s2, acc[6][2]);
            acc[6][3] = ffma2(a67.x, s3, acc[6][3]);
            acc[7][0] = ffma2(a67.y, s0, acc[7][0]);
            acc[7][1] = ffma2(a67.y, s1, acc[7][1]);
            acc[7][2] = ffma2(a67.y, s2, acc[7][2]);
            acc[7][3] = ffma2(a67.y, s3, acc[7][3]);
        }

        if (more) {
            __syncthreads();
            STORE_TILE(cur ^ 1)
        }
    }

    // ---- store raw fp32 partials: 16 rows x 1 float4, guarded for tail tiles
    #pragma unroll
    for (int rp = 0; rp < 8; rp++) {
        const int row0 = m0 + ty * 16 + rp * 2;
        float2 u0 = unpack2(acc[rp][0]);
        float2 u1 = unpack2(acc[rp][1]);
        float2 u2 = unpack2(acc[rp][2]);
        float2 u3 = unpack2(acc[rp][3]);
        if (row0 < Mrows) {
            float4 o = make_float4(u0.x, u1.x, u2.x, u3.x);
            *(float4*)&Cp[row0 * PP + n0 + tx * 4] = o;
        }
        if (row0 + 1 < Mrows) {
            float4 o = make_float4(u0.y, u1.y, u2.y, u3.y);
            *(float4*)&Cp[(row0 + 1) * PP + n0 + tx * 4] = o;
        }
    }
}

// ---------------- Kernel 2: reduce split-K partials + bias + exact GELU -------
#define QN4 (BB * TT * PP / 4)     // 65536 float4
#define KN4 (BB * RR * PP / 4)     // 102400 float4
__global__ __launch_bounds__(256) void reduce_gelu_kernel(
    const float* __restrict__ bq, const float* __restrict__ bk)
{
    int i = blockIdx.x * 256 + threadIdx.x;
    const float4 *p0, *bs; float4* dst; int stride, nsum;
    if (i < QN4) {
        p0 = (const float4*)g_pq; stride = QN4; nsum = QSPLIT;
        bs = (const float4*)bq;   dst = (float4*)g_q;
    } else {
        i -= QN4;
        p0 = (const float4*)g_pk; stride = KN4; nsum = KSPLIT;
        bs = (const float4*)bk;   dst = (float4*)g_k;
    }
    float4 bz = bs[i & 127];
    float4 s = p0[i];
    for (int h = 1; h < nsum; h++) {
        float4 v = p0[i + h * stride];
        s.x += v.x; s.y += v.y; s.z += v.z; s.w += v.w;
    }
    float4 o;
    o.x = gelu_exact(s.x + bz.x);
    o.y = gelu_exact(s.y + bz.y);
    o.z = gelu_exact(s.z + bz.z);
    o.w = gelu_exact(s.w + bz.w);
    dst[i] = o;
}

// ---------------- Kernel 3: fusion + tanh + weighted reduce -------------------
// grid = B*T = 512 blocks, 256 threads (8 warps). One (b,t) per block.
// q row + w in registers; r-pairs per iteration with interleaved shfl chains.
__global__ __launch_bounds__(256) void fusion_kernel(
    const float* __restrict__ mask, const float* __restrict__ w,
    const float* __restrict__ bptr, float* __restrict__ out)
{
    const int b = blockIdx.x >> 6;          // /TT
    const int t = blockIdx.x & 63;          // %TT
    const int warp = threadIdx.x >> 5, lane = threadIdx.x & 31;

    const float4* q4 = (const float4*)&g_q[(b * TT + t) * PP];
    const float4* w4 = (const float4*)w;
    const float4* kbase = (const float4*)&g_k[(size_t)b * RR * PP];

    float4 qv[4], wv[4];
    #pragma unroll
    for (int j = 0; j < 4; j++) {
        qv[j] = q4[lane + j * 32];
        wv[j] = w4[lane + j * 32];
    }

    const float bb = bptr[0];
    const int obase = (b * TT + t) * RR;

    for (int j = 0; j < 7; j++) {
        const int r0 = warp + j * 16;
        const int r1 = r0 + 8;
        const bool v0 = r0 < RR, v1 = r1 < RR;

        float4 k0[4], k1[4];
        if (v0) {
            #pragma unroll
            for (int u = 0; u < 4; u++) k0[u] = kbase[r0 * 128 + lane + u * 32];
        }
        if (v1) {
            #pragma unroll
            for (int u = 0; u < 4; u++) k1[u] = kbase[r1 * 128 + lane + u * 32];
        }

        float a0 = 0.f, a1 = 0.f, a2 = 0.f, a3 = 0.f;
        float c0 = 0.f, c1 = 0.f, c2 = 0.f, c3 = 0.f;
        if (v0) {
            #pragma unroll
            for (int u = 0; u < 4; u++) {
                a0 += tanh_approx(qv[u].x + k0[u].x) * wv[u].x;
                a1 += tanh_approx(qv[u].y + k0[u].y) * wv[u].y;
                a2 += tanh_approx(qv[u].z + k0[u].z) * wv[u].z;
                a3 += tanh_approx(qv[u].w + k0[u].w) * wv[u].w;
            }
        }
        if (v1) {
            #pragma unroll
            for (int u = 0; u < 4; u++) {
                c0 += tanh_approx(qv[u].x + k1[u].x) * wv[u].x;
                c1 += tanh_approx(qv[u].y + k1[u].y) * wv[u].y;
                c2 += tanh_approx(qv[u].z + k1[u].z) * wv[u].z;
                c3 += tanh_approx(qv[u].w + k1[u].w) * wv[u].w;
            }
        }

        float s0 = (a0 + a1) + (a2 + a3);
        float s1 = (c0 + c1) + (c2 + c3);
        #pragma unroll
        for (int off = 16; off; off >>= 1) {
            s0 += __shfl_xor_sync(0xffffffffu, s0, off);
            s1 += __shfl_xor_sync(0xffffffffu, s1, off);
        }
        if (lane == 0) {
            if (v0) out[obase + r0] = s0 + bb + mask[obase + r0];
            if (v1) out[obase + r1] = s1 + bb + mask[obase + r1];
        }
    }
}

// ---------------- launch ------------------------------------------------------
extern "C" void kernel_launch(void* const* d_in, const int* in_sizes, int n_in,
                              void* d_out, int out_size) {
    const float* encT = (const float*)d_in[0];
    const float* encI = (const float*)d_in[1];
    const float* mask = (const float*)d_in[2];
    const float* Wq   = (const float*)d_in[3];
    const float* bq   = (const float*)d_in[4];
    const float* Wk   = (const float*)d_in[5];
    const float* bk   = (const float*)d_in[6];
    const float* w    = (const float*)d_in[7];
    const float* bp   = (const float*)d_in[8];
    float* out = (float*)d_out;

    gemm_part_kernel<<<448 + 32 * QSPLIT, 128>>>(encT, Wq, encI, Wk);
    reduce_gelu_kernel<<<(QN4 + KN4) / 256, 256>>>(bq, bk);
    fusion_kernel<<<BB * TT, 256>>>(mask, w, bp, out);
}

// round 16
// speedup vs baseline: 1.0827x; 1.0827x over previous
#include <cuda_runtime.h>
#include <math.h>
#include <stdint.h>

// Fixed problem shapes (from setup_inputs)
#define BB   8
#define TT   64
#define RR   100
#define TH   768
#define IH   1024
#define PP   512

// Final activations
__device__ float g_q[BB * TT * PP];          // [512][512]
__device__ float g_k[BB * RR * PP];          // [800][512]
// Split-K partials: uniform 128-wide K-chunks (q: 6 chunks, k: 8 chunks)
#define QSPLIT 6
#define KSPLIT 8
__device__ float g_pq[QSPLIT * BB * TT * PP];
__device__ float g_pk[KSPLIT * BB * RR * PP];
// Pre-transposed A matrices (A^T[k][m]); k-matrix m-padded 800->896 with zeros
#define MPAD_K 896
#define MQ     (BB * TT)       // 512
__device__ float g_kT[IH * MPAD_K];
__device__ float g_qT[TH * MQ];

typedef unsigned long long ull;

// ---------------- f32x2 helpers (Blackwell packed fp32) -----------------------
__device__ __forceinline__ ull ffma2(ull a, ull b, ull c) {
    ull d;
    asm("fma.rn.f32x2 %0, %1, %2, %3;" : "=l"(d) : "l"(a), "l"(b), "l"(c));
    return d;
}
__device__ __forceinline__ float2 unpack2(ull v) {
    float2 f;
    asm("mov.b64 {%0, %1}, %2;" : "=f"(f.x), "=f"(f.y) : "l"(v));
    return f;
}
__device__ __forceinline__ ull dup2(float x) {
    ull r;
    asm("mov.b64 %0, {%1, %1};" : "=l"(r) : "f"(x));
    return r;
}
__device__ __forceinline__ void cpa16(uint32_t s, const void* g) {
    asm volatile("cp.async.cg.shared.global [%0], [%1], 16;" :: "r"(s), "l"(g));
}

__device__ __forceinline__ float gelu_exact(float x) {
    return 0.5f * x * (1.0f + erff(x * 0.70710678118654752440f));
}

__device__ __forceinline__ float tanh_approx(float x) {
    float y;
    asm("tanh.approx.f32 %0, %1;" : "=f"(y) : "f"(x));
    return y;
}

// ---------------- Kernel 0: transpose A matrices ------------------------------
// encI[800][1024] -> g_kT[1024][896] (zero-fill m in [800,896))
// encT[512][768]  -> g_qT[768][512]
__global__ __launch_bounds__(256) void transpose_kernel(
    const float* __restrict__ encI, const float* __restrict__ encT)
{
    __shared__ float ts[32][33];
    int bid = blockIdx.x;
    const float* in; float* out; int K, Mreal, Mpad, kt, mt;
    if (bid < 896) {                       // 32 k-tiles x 28 m-tiles
        in = encI; out = g_kT; K = IH; Mreal = 800; Mpad = MPAD_K;
        kt = bid & 31; mt = bid >> 5;
    } else {                               // 24 k-tiles x 16 m-tiles
        bid -= 896;
        in = encT; out = g_qT; K = TH; Mreal = 512; Mpad = 512;
        kt = bid % 24; mt = bid / 24;
    }
    const int k0 = kt * 32, m0 = mt * 32;
    const int tx = threadIdx.x & 31, tyy = threadIdx.x >> 5;
    #pragma unroll
    for (int i = 0; i < 4; i++) {
        int m = m0 + tyy + i * 8;
        ts[tyy + i * 8][tx] = (m < Mreal) ? in[m * K + k0 + tx] : 0.0f;
    }
    __syncthreads();
    #pragma unroll
    for (int i = 0; i < 4; i++) {
        int k = k0 + tyy + i * 8;
        out[k * Mpad + m0 + tx] = ts[tx][tyy + i * 8];
    }
}

// ---------------- Kernel 1: split-K GEMM, cp.async 3-stage --------------------
// Block tile 128(M) x 64(N) x 16(K), 128 threads, thread = 16 rows x 4 cols.
// A comes PRE-TRANSPOSED (g_kT/g_qT) so tiles copy in via cp.async with no
// register staging and no STS transpose. 3 smem stages -> ONE __syncthreads
// per tile-iter (WAR-safe: writes go 2 buffers ahead of the one being read).
//   blocks [0,448)   : k-GEMM (7x8 tiles x 8 chunks)
//   blocks [448,640) : q-GEMM (4x8 tiles x 6 chunks)
#define GBM 128
#define GBN 64
#define GBK 16
#define KCHUNK 128

__global__ __launch_bounds__(128, 4) void gemm_part_kernel(
    const float* __restrict__ Wq, const float* __restrict__ Wk)
{
    __shared__ __align__(16) float Ast[3][GBK][GBM + 4];   // A^T tile [k][m], stride 132
    __shared__ __align__(16) float Ws[3][GBK][GBN];

    int bid = blockIdx.x;
    const float* AT; const float* W; float* Cp;
    int Ms, Mrows, tile, half;
    if (bid < 448) {
        tile = bid >> 3; half = bid & 7;
        AT = g_kT; W = Wk; Ms = MPAD_K; Mrows = BB * RR;     // 800
        Cp = g_pk + half * (BB * RR * PP);
    } else {
        bid -= 448;
        tile = bid / QSPLIT; half = bid - tile * QSPLIT;
        AT = g_qT; W = Wq; Ms = MQ; Mrows = BB * TT;          // 512
        Cp = g_pq + half * (BB * TT * PP);
    }
    const int mt = tile >> 3, nt = tile & 7;
    const int m0 = mt * GBM;
    const int n0 = nt * GBN;
    const int kstart = half * KCHUNK;
    const int niter = KCHUNK / GBK;      // 8, uniform

    const int tid = threadIdx.x;
    const int tx = tid & 15;     // cols tx*4 .. +3
    const int ty = tid >> 4;     // rows ty*16 .. +15 (8 row-pairs)

    // cp.async loader coords: each thread copies 4x16B of A + 2x16B of W
    const int lk = tid >> 3;             // k-row 0..15
    const int lac = (tid & 7) * 16;      // A float offset within row (64B seg)
    const int lwc = (tid & 7) * 8;       // W float offset within row (32B seg)

    ull acc[8][4];               // [rowpair][col]
    #pragma unroll
    for (int i = 0; i < 8; i++)
        #pragma unroll
        for (int j = 0; j < 4; j++) acc[i][j] = 0ull;

    // device lambda (no macro line-continuation hazards)
    auto issue_tile = [&](int buf, int k0) {
        uint32_t sa = (uint32_t)__cvta_generic_to_shared(&Ast[buf][lk][lac]);
        const float* ga = &AT[(k0 + lk) * Ms + m0 + lac];
        cpa16(sa,      ga);
        cpa16(sa + 16, ga + 4);
        cpa16(sa + 32, ga + 8);
        cpa16(sa + 48, ga + 12);
        uint32_t sw = (uint32_t)__cvta_generic_to_shared(&Ws[buf][lk][lwc]);
        const float* gw = &W[(k0 + lk) * PP + n0 + lwc];
        cpa16(sw,      gw);
        cpa16(sw + 16, gw + 4);
        asm volatile("cp.async.commit_group;");
    };

    issue_tile(0, kstart);
    issue_tile(1, kstart + GBK);

    for (int it = 0; it < niter; it++) {
        asm volatile("cp.async.wait_group %0;" :: "n"(1));
        __syncthreads();
        const int cur = it % 3;

        #pragma unroll
        for (int kk = 0; kk < GBK; kk++) {
            ulonglong2 a01 = *(const ulonglong2*)&Ast[cur][kk][ty * 16];
            ulonglong2 a23 = *(const ulonglong2*)&Ast[cur][kk][ty * 16 + 4];
            ulonglong2 a45 = *(const ulonglong2*)&Ast[cur][kk][ty * 16 + 8];
            ulonglong2 a67 = *(const ulonglong2*)&Ast[cur][kk][ty * 16 + 12];
            float4 bv = *(const float4*)&Ws[cur][kk][tx * 4];
            ull s0 = dup2(bv.x), s1 = dup2(bv.y), s2 = dup2(bv.z), s3 = dup2(bv.w);

            acc[0][0] = ffma2(a01.x, s0, acc[0][0]);
            acc[0][1] = ffma2(a01.x, s1, acc[0][1]);
            acc[0][2] = ffma2(a01.x, s2, acc[0][2]);
            acc[0][3] = ffma2(a01.x, s3, acc[0][3]);
            acc[1][0] = ffma2(a01.y, s0, acc[1][0]);
            acc[1][1] = ffma2(a01.y, s1, acc[1][1]);
            acc[1][2] = ffma2(a01.y, s2, acc[1][2]);
            acc[1][3] = ffma2(a01.y, s3, acc[1][3]);
            acc[2][0] = ffma2(a23.x, s0, acc[2][0]);
            acc[2][1] = ffma2(a23.x, s1, acc[2][1]);
            acc[2][2] = ffma2(a23.x, s2, acc[2][2]);
            acc[2][3] = ffma2(a23.x, s3, acc[2][3]);
            acc[3][0] = ffma2(a23.y, s0, acc[3][0]);
            acc[3][1] = ffma2(a23.y, s1, acc[3][1]);
            acc[3][2] = ffma2(a23.y, s2, acc[3][2]);
            acc[3][3] = ffma2(a23.y, s3, acc[3][3]);
            acc[4][0] = ffma2(a45.x, s0, acc[4][0]);
            acc[4][1] = ffma2(a45.x, s1, acc[4][1]);
            acc[4][2] = ffma2(a45.x, s2, acc[4][2]);
            acc[4][3] = ffma2(a45.x, s3, acc[4][3]);
            acc[5][0] = ffma2(a45.y, s0, acc[5][0]);
            acc[5][1] = ffma2(a45.y, s1, acc[5][1]);
            acc[5][2] = ffma2(a45.y, s2, acc[5][2]);
            acc[5][3] = ffma2(a45.y, s3, acc[5][3]);
            acc[6][0] = ffma2(a67.x, s0, acc[6][0]);
            acc[6][1] = ffma2(a67.x, s1, acc[6][1]);
            acc[6][2] = ffma2(a67.x, s2, acc[6][2]);
            acc[6][3] = ffma2(a67.x, s3, acc[6][3]);
            acc[7][0] = ffma2(a67.y, s0, acc[7][0]);
            acc[7][1] = ffma2(a67.y, s1, acc[7][1]);
            acc[7][2] = ffma2(a67.y, s2, acc[7][2]);
            acc[7][3] = ffma2(a67.y, s3, acc[7][3]);
        }

        if (it + 2 < niter) issue_tile((it + 2) % 3, kstart + (it + 2) * GBK);
    }

    // ---- store raw fp32 partials: 16 rows x 1 float4, guarded for tail tiles
    #pragma unroll
    for (int rp = 0; rp < 8; rp++) {
        const int row0 = m0 + ty * 16 + rp * 2;
        float2 u0 = unpack2(acc[rp][0]);
        float2 u1 = unpack2(acc[rp][1]);
        float2 u2 = unpack2(acc[rp][2]);
        float2 u3 = unpack2(acc[rp][3]);
        if (row0 < Mrows) {
            float4 o = make_float4(u0.x, u1.x, u2.x, u3.x);
            *(float4*)&Cp[row0 * PP + n0 + tx * 4] = o;
        }
        if (row0 + 1 < Mrows) {
            float4 o = make_float4(u0.y, u1.y, u2.y, u3.y);
            *(float4*)&Cp[(row0 + 1) * PP + n0 + tx * 4] = o;
        }
    }
}

// ---------------- Kernel 2: reduce split-K partials + bias + exact GELU -------
#define QN4 (BB * TT * PP / 4)     // 65536 float4
#define KN4 (BB * RR * PP / 4)     // 102400 float4
__global__ __launch_bounds__(256) void reduce_gelu_kernel(
    const float* __restrict__ bq, const float* __restrict__ bk)
{
    int i = blockIdx.x * 256 + threadIdx.x;
    const float4 *p0, *bs; float4* dst; int stride, nsum;
    if (i < QN4) {
        p0 = (const float4*)g_pq; stride = QN4; nsum = QSPLIT;
        bs = (const float4*)bq;   dst = (float4*)g_q;
    } else {
        i -= QN4;
        p0 = (const float4*)g_pk; stride = KN4; nsum = KSPLIT;
        bs = (const float4*)bk;   dst = (float4*)g_k;
    }
    float4 bz = bs[i & 127];
    float4 s = p0[i];
    for (int h = 1; h < nsum; h++) {
        float4 v = p0[i + h * stride];
        s.x += v.x; s.y += v.y; s.z += v.z; s.w += v.w;
    }
    float4 o;
    o.x = gelu_exact(s.x + bz.x);
    o.y = gelu_exact(s.y + bz.y);
    o.z = gelu_exact(s.z + bz.z);
    o.w = gelu_exact(s.w + bz.w);
    dst[i] = o;
}

// ---------------- Kernel 3: fusion + tanh + weighted reduce -------------------
// grid = B*T*2 = 1024 blocks (2 blocks per (b,t), each owns 50 r's) for
// better latency hiding; 256 threads (8 warps), q row + w in registers,
// r-pairs per iteration with interleaved shfl chains.
__global__ __launch_bounds__(256) void fusion_kernel(
    const float* __restrict__ mask, const float* __restrict__ w,
    const float* __restrict__ bptr, float* __restrict__ out)
{
    const int bid = blockIdx.x;
    const int h = bid & 1;                  // r-half
    const int bt = bid >> 1;                // 0..511
    const int b = bt >> 6;
    const int t = bt & 63;
    const int warp = threadIdx.x >> 5, lane = threadIdx.x & 31;

    const float4* q4 = (const float4*)&g_q[(b * TT + t) * PP];
    const float4* w4 = (const float4*)w;
    const float4* kbase = (const float4*)&g_k[(size_t)b * RR * PP];

    float4 qv[4], wv[4];
    #pragma unroll
    for (int j = 0; j < 4; j++) {
        qv[j] = q4[lane + j * 32];
        wv[j] = w4[lane + j * 32];
    }

    const float bb = bptr[0];
    const int obase = (b * TT + t) * RR;
    const int rbase = h * 50;

    #pragma unroll
    for (int j = 0; j < 4; j++) {
        const int o0 = warp + j * 16;
        const int o1 = o0 + 8;
        const bool v0 = o0 < 50, v1 = o1 < 50;
        const int r0 = rbase + o0, r1 = rbase + o1;

        float4 k0[4], k1[4];
        if (v0) {
            #pragma unroll
            for (int u = 0; u < 4; u++) k0[u] = kbase[r0 * 128 + lane + u * 32];
        }
        if (v1) {
            #pragma unroll
            for (int u = 0; u < 4; u++) k1[u] = kbase[r1 * 128 + lane + u * 32];
        }

        float a0 = 0.f, a1 = 0.f, a2 = 0.f, a3 = 0.f;
        float c0 = 0.f, c1 = 0.f, c2 = 0.f, c3 = 0.f;
        if (v0) {
            #pragma unroll
            for (int u = 0; u < 4; u++) {
                a0 += tanh_approx(qv[u].x + k0[u].x) * wv[u].x;
                a1 += tanh_approx(qv[u].y + k0[u].y) * wv[u].y;
                a2 += tanh_approx(qv[u].z + k0[u].z) * wv[u].z;
                a3 += tanh_approx(qv[u].w + k0[u].w) * wv[u].w;
            }
        }
        if (v1) {
            #pragma unroll
            for (int u = 0; u < 4; u++) {
                c0 += tanh_approx(qv[u].x + k1[u].x) * wv[u].x;
                c1 += tanh_approx(qv[u].y + k1[u].y) * wv[u].y;
                c2 += tanh_approx(qv[u].z + k1[u].z) * wv[u].z;
                c3 += tanh_approx(qv[u].w + k1[u].w) * wv[u].w;
            }
        }

        float s0 = (a0 + a1) + (a2 + a3);
        float s1 = (c0 + c1) + (c2 + c3);
        #pragma unroll
        for (int off = 16; off; off >>= 1) {
            s0 += __shfl_xor_sync(0xffffffffu, s0, off);
            s1 += __shfl_xor_sync(0xffffffffu, s1, off);
        }
        if (lane == 0) {
            if (v0) out[obase + r0] = s0 + bb + mask[obase + r0];
            if (v1) out[obase + r1] = s1 + bb + mask[obase + r1];
        }
    }
}

// ---------------- launch ------------------------------------------------------
extern "C" void kernel_launch(void* const* d_in, const int* in_sizes, int n_in,
                              void* d_out, int out_size) {
    const float* encT = (const float*)d_in[0];
    const float* encI = (const float*)d_in[1];
    const float* mask = (const float*)d_in[2];
    const float* Wq   = (const float*)d_in[3];
    const float* bq   = (const float*)d_in[4];
    const float* Wk   = (const float*)d_in[5];
    const float* bk   = (const float*)d_in[6];
    const float* w    = (const float*)d_in[7];
    const float* bp   = (const float*)d_in[8];
    float* out = (float*)d_out;

    transpose_kernel<<<1280, 256>>>(encI, encT);
    gemm_part_kernel<<<448 + 32 * QSPLIT, 128>>>(Wq, Wk);
    reduce_gelu_kernel<<<(QN4 + KN4) / 256, 256>>>(bq, bk);
    fusion_kernel<<<BB * TT * 2, 256>>>(mask, w, bp, out);
}